// round 1
// baseline (speedup 1.0000x reference)
#include <cuda_runtime.h>

// Inv1x1ConvPermute: kernel matrix is a permutation matrix (shuffled identity).
// out[b,t,o] = x[b,t, src_of[o]] where src_of[perm[i]] = i, perm[i] = argmax kernel[i,:].
//
// Phase 1: extract permutation from the 256x256 kernel (branch-free one-hot dot).
// Phase 2: DRAM-bound channel gather, 512 MiB total traffic.

#define C 256
#define ROWS_PER_BLOCK 4

__device__ int g_src[C];  // g_src[o] = input channel feeding output channel o

__global__ void build_perm_kernel(const float* __restrict__ kmat) {
    int i = threadIdx.x;  // input channel, 0..255
    const float4* row = reinterpret_cast<const float4*>(kmat + i * C);
    float acc = 0.0f;
#pragma unroll
    for (int q = 0; q < C / 4; ++q) {
        float4 v = row[q];
        int o = q * 4;
        acc += (float)(o + 0) * v.x;
        acc += (float)(o + 1) * v.y;
        acc += (float)(o + 2) * v.z;
        acc += (float)(o + 3) * v.w;
    }
    int perm_i = (int)(acc + 0.5f);  // row i is one-hot at column perm_i
    g_src[perm_i] = i;
}

__global__ __launch_bounds__(256) void gather_kernel(const float* __restrict__ x,
                                                     float* __restrict__ out) {
    __shared__ float s[ROWS_PER_BLOCK][C];

    int tid  = threadIdx.x;          // 0..255
    int r    = tid >> 6;             // row within block, 0..3
    int lane = tid & 63;             // float4 slot within row, 0..63

    long long row0 = (long long)blockIdx.x * ROWS_PER_BLOCK;
    long long base = (row0 + r) * C;

    // Per-thread source indices for its 4 output channels (coalesced int4 load, L1/L2 cached)
    int4 src = reinterpret_cast<const int4*>(g_src)[lane];

    // Coalesced load: 4 rows x 1KB into shared
    float4 v = reinterpret_cast<const float4*>(x + base)[lane];
    *reinterpret_cast<float4*>(&s[r][lane * 4]) = v;
    __syncthreads();

    // Gather through shared, coalesced float4 store
    float4 o4;
    o4.x = s[r][src.x];
    o4.y = s[r][src.y];
    o4.z = s[r][src.z];
    o4.w = s[r][src.w];
    reinterpret_cast<float4*>(out + base)[lane] = o4;
}

extern "C" void kernel_launch(void* const* d_in, const int* in_sizes, int n_in,
                              void* d_out, int out_size) {
    const float* x    = (const float*)d_in[0];   // [B,T,C] = [16,16384,256]
    const float* kmat = (const float*)d_in[1];   // [C,C] permutation matrix
    float* out        = (float*)d_out;

    // total rows = B*T
    long long total = (long long)in_sizes[0];    // B*T*C elements
    int nrows = (int)(total / C);                // 262144

    build_perm_kernel<<<1, C>>>(kmat);

    int grid = nrows / ROWS_PER_BLOCK;           // 65536 blocks
    gather_kernel<<<grid, 256>>>(x, out);
}

// round 2
// speedup vs baseline: 1.1734x; 1.1734x over previous
#include <cuda_runtime.h>

// Inv1x1ConvPermute: kernel matrix is a permutation matrix (shuffled identity).
// out[b,t,o] = x[b,t, src[o]] -- a pure channel gather. DRAM-bound: 512 MiB traffic.
//
// Phase 1: extract permutation, fully parallel (256 blocks, one element/thread).
// Phase 2: warp-autonomous gather: each warp owns 2 rows, MLP=4 loads, no block barrier.

#define C 256
#define WARPS_PER_BLOCK 8
#define ROWS_PER_WARP 2
#define ROWS_PER_BLOCK (WARPS_PER_BLOCK * ROWS_PER_WARP)   // 16

__device__ int g_src[C];  // g_src[o] = input channel feeding output channel o

__global__ void build_perm_kernel(const float* __restrict__ kmat) {
    int i = blockIdx.x;      // input channel (row)
    int o = threadIdx.x;     // output channel (col)
    // row i of the permutation matrix is one-hot: kmat[i][o]==1 iff perm[i]==o
    if (kmat[i * C + o] != 0.0f) {
        g_src[o] = i;
    }
}

__global__ __launch_bounds__(256) void gather_kernel(const float* __restrict__ x,
                                                     float* __restrict__ out) {
    __shared__ float s[ROWS_PER_BLOCK][C];

    int tid  = threadIdx.x;
    int w    = tid >> 5;     // warp 0..7
    int lane = tid & 31;

    long long row0 = ((long long)blockIdx.x * WARPS_PER_BLOCK + w) * ROWS_PER_WARP;

    // Per-lane source indices for float4 slots (lane) and (lane+32), held in regs.
    int4 src0 = reinterpret_cast<const int4*>(g_src)[lane];
    int4 src1 = reinterpret_cast<const int4*>(g_src)[lane + 32];

    // Front-batched loads: 4 independent float4 (MLP=4), streaming (no reuse).
    const float4* xin = reinterpret_cast<const float4*>(x + row0 * C);
    float4 v00 = __ldcs(&xin[lane]);         // row 0, first half
    float4 v01 = __ldcs(&xin[lane + 32]);    // row 0, second half
    float4 v10 = __ldcs(&xin[lane + 64]);    // row 1, first half
    float4 v11 = __ldcs(&xin[lane + 96]);    // row 1, second half

    float* r0 = s[w * ROWS_PER_WARP + 0];
    float* r1 = s[w * ROWS_PER_WARP + 1];
    *reinterpret_cast<float4*>(&r0[lane * 4])        = v00;
    *reinterpret_cast<float4*>(&r0[(lane + 32) * 4]) = v01;
    *reinterpret_cast<float4*>(&r1[lane * 4])        = v10;
    *reinterpret_cast<float4*>(&r1[(lane + 32) * 4]) = v11;
    __syncwarp();

    // Gather + coalesced streaming stores.
    float4* oout = reinterpret_cast<float4*>(out + row0 * C);
    float4 o00, o01, o10, o11;
    o00.x = r0[src0.x]; o00.y = r0[src0.y]; o00.z = r0[src0.z]; o00.w = r0[src0.w];
    o01.x = r0[src1.x]; o01.y = r0[src1.y]; o01.z = r0[src1.z]; o01.w = r0[src1.w];
    o10.x = r1[src0.x]; o10.y = r1[src0.y]; o10.z = r1[src0.z]; o10.w = r1[src0.w];
    o11.x = r1[src1.x]; o11.y = r1[src1.y]; o11.z = r1[src1.z]; o11.w = r1[src1.w];
    __stcs(&oout[lane],      o00);
    __stcs(&oout[lane + 32], o01);
    __stcs(&oout[lane + 64], o10);
    __stcs(&oout[lane + 96], o11);
}

extern "C" void kernel_launch(void* const* d_in, const int* in_sizes, int n_in,
                              void* d_out, int out_size) {
    const float* x    = (const float*)d_in[0];   // [B,T,C] = [16,16384,256]
    const float* kmat = (const float*)d_in[1];   // [C,C] permutation matrix
    float* out        = (float*)d_out;

    long long total = (long long)in_sizes[0];    // B*T*C elements
    int nrows = (int)(total / C);                // 262144

    build_perm_kernel<<<C, C>>>(kmat);

    int grid = nrows / ROWS_PER_BLOCK;           // 16384 blocks
    gather_kernel<<<grid, 256>>>(x, out);
}